// round 8
// baseline (speedup 1.0000x reference)
#include <cuda_runtime.h>

#define NB    4
#define P1N   8192
#define P2N   8192
#define KK    16
#define TILE  2048
#define BLOCK 256

// XLA GPU small-row reduce: row of 3 padded to 4 lanes (4th = init 0),
// warp-shuffle butterfly with offsets 2 then 1:
//   stage1: x^2 + z^2   (lanes 0+2),  y^2 + 0  (lanes 1+3)
//   stage2: (x^2 + z^2) + y^2
// All squares individually rounded (separate fmul in the fused producer).
__device__ __forceinline__ float sumsq3(float x, float y, float z) {
    return __fadd_rn(__fadd_rn(__fmul_rn(x, x), __fmul_rn(z, z)),
                     __fmul_rn(y, y));
}

__global__ __launch_bounds__(BLOCK) void knn_topk_kernel(
    const float* __restrict__ p1,
    const float* __restrict__ p2,
    float* __restrict__ out)
{
    __shared__ float4 sm[TILE];

    const int blocks_per_batch = P1N / BLOCK;          // 32
    const int n = blockIdx.x / blocks_per_batch;       // batch
    const int q = (blockIdx.x % blocks_per_batch) * BLOCK + threadIdx.x;

    const float* p1r = p1 + ((size_t)n * P1N + q) * 3;
    const float x1 = p1r[0];
    const float y1 = p1r[1];
    const float z1 = p1r[2];
    const float sq1 = sumsq3(x1, y1, z1);

    // top-K kept as a DESCENDING sorted list in registers:
    // dq[0] = current worst (max), dq[15] = best (min)
    float dq[KK];
    int   iq[KK];
    const float INF = __int_as_float(0x7f800000);
#pragma unroll
    for (int i = 0; i < KK; i++) { dq[i] = INF; iq[i] = 0; }

    const float* p2b = p2 + (size_t)n * P2N * 3;

    for (int t = 0; t < P2N; t += TILE) {
        __syncthreads();
        // stage p2 tile into shared as (x,y,z,||p||^2)
        for (int i = threadIdx.x; i < TILE; i += BLOCK) {
            const float* pr = p2b + (size_t)(t + i) * 3;
            float x = pr[0], y = pr[1], z = pr[2];
            sm[i] = make_float4(x, y, z, sumsq3(x, y, z));
        }
        __syncthreads();

        float worst = dq[0];
#pragma unroll 4
        for (int jj = 0; jj < TILE; jj++) {
            float4 s = sm[jj];
            // inner: cuBLAS FFMA sgemm, k ascending, acc from exact 0:
            // fma(z, fma(y, rn(x*x2)))
            float inr = __fmaf_rn(z1, s.z,
                         __fmaf_rn(y1, s.y,
                          __fmul_rn(x1, s.x)));
            // d = (sq1 + sq2) - 2*inner (Sterbenz: == fma(-2,I,S))
            float d = __fsub_rn(__fadd_rn(sq1, s.w), __fmul_rn(2.0f, inr));

            // strict '<': lowest index wins exact ties (proven by R4)
            if (d < worst) {
                int j = t + jj;
                bool pprev = true;
#pragma unroll
                for (int i = 0; i < KK - 1; i++) {
                    bool pi = d < dq[i + 1];
                    float nd = pi ? dq[i + 1] : (pprev ? d : dq[i]);
                    int   ni = pi ? iq[i + 1] : (pprev ? j : iq[i]);
                    dq[i] = nd;
                    iq[i] = ni;
                    pprev = pi;
                }
                dq[KK - 1] = pprev ? d : dq[KK - 1];
                iq[KK - 1] = pprev ? j : iq[KK - 1];
                worst = dq[0];
            }
        }
    }

    // Output: concat(idxs (N,P1,K) as float32, dists (N,P1,K)), ascending rows.
    const size_t base = ((size_t)n * P1N + q) * KK;
    const size_t NPK  = (size_t)NB * P1N * KK;
#pragma unroll
    for (int k = 0; k < KK; k++) {
        out[base + k]       = (float)iq[KK - 1 - k];
        out[NPK + base + k] = dq[KK - 1 - k];
    }
}

extern "C" void kernel_launch(void* const* d_in, const int* in_sizes, int n_in,
                              void* d_out, int out_size)
{
    const float* p1 = (const float*)d_in[0];
    const float* p2 = (const float*)d_in[1];
    float* out = (float*)d_out;

    dim3 grid(NB * (P1N / BLOCK));  // 128 blocks, one full wave
    dim3 block(BLOCK);
    knn_topk_kernel<<<grid, block>>>(p1, p2, out);
}